// round 14
// baseline (speedup 1.0000x reference)
#include <cuda_runtime.h>
#include <cuda.h>
#include <cuda_bf16.h>
#include <cuda_fp16.h>
#include <math.h>
#include <stdint.h>

#define BB 32
#define CC 384
#define LL 3136
#define HIMG 56
#define HEADS 12
#define DH 32
#define NK 784

typedef __nv_bfloat16 bf16;

// ---------------- scratch (device globals; no allocation allowed) ----------
__device__ __align__(16) bf16 g_yq[(size_t)BB*LL*CC];   // dwconv out (bf16), [b,n,c]
__device__ __align__(16) bf16 g_yk[(size_t)BB*NK*CC];
__device__ __align__(16) bf16 g_yv[(size_t)BB*NK*CC];
__device__ float g_stats[3*CC*2];
__device__ __align__(16) bf16 g_Wp[(size_t)3*CC*CC];    // BN-folded pointwise weights
__device__ float g_bp[3*CC];
__device__ __align__(16) bf16 g_qact[(size_t)BB*LL*CC]; // q act bf16 [b,n,c]
__device__ __align__(16) bf16 g_kact[(size_t)BB*NK*CC]; // k act bf16
__device__ __align__(16) bf16 g_vact[(size_t)BB*NK*CC]; // v act bf16
__device__ float g_kv[(size_t)BB*HEADS*DH*DH];
__device__ __align__(16) __half g_yh[(size_t)BB*CC*LL]; // pre-BN1 y (fp16), [b,c,l]
__device__ float g_bn1s[CC*2];
__device__ float g_bn1f[CC*2];

// ---------------- helpers ---------------------------------------------------
__device__ __forceinline__ uint32_t smem_u32(const void* p) {
    uint32_t a;
    asm("{ .reg .u64 t; cvta.to.shared.u64 t, %1; cvt.u32.u64 %0, t; }" : "=r"(a) : "l"(p));
    return a;
}
#define CP_ASYNC16(dst, src) \
    asm volatile("cp.async.cg.shared.global [%0], [%1], 16;" :: "r"(dst), "l"(src))
#define CP_COMMIT() asm volatile("cp.async.commit_group;" ::: "memory")
#define CP_WAITN(n) asm volatile("cp.async.wait_group %0;" :: "n"(n) : "memory")
#define LDSM_X4(r0, r1, r2, r3, addr) \
    asm volatile("ldmatrix.sync.aligned.m8n8.x4.shared.b16 {%0,%1,%2,%3}, [%4];" \
        : "=r"(r0), "=r"(r1), "=r"(r2), "=r"(r3) : "r"(addr))

// ---------------- kernels --------------------------------------------------

__global__ void zero_stats_kernel() {
    int i = blockIdx.x * blockDim.x + threadIdx.x;
    if (i < 3*CC*2) g_stats[i] = 0.f;
    if (i < CC*2)   g_bn1s[i]  = 0.f;
}

// Fused depthwise 3x3 (3 branches), transposed bf16 output [b,n,c], BN stats.
#define CHS 581
__global__ void dwconv_fused(const float* __restrict__ x,
                             const float* __restrict__ dwk) {
    extern __shared__ float xs[];
    __shared__ float bacc[3*32*2];
    int strip = blockIdx.x, cg = blockIdx.y, b = blockIdx.z;
    int tid = threadIdx.x;
    int w = tid >> 5, lane = tid & 31;
    int cglob = cg * 32;
    int c = cglob + lane;

    if (tid < 192) bacc[tid] = 0.f;
    for (int i = tid; i < 32*CHS; i += 256) xs[i] = 0.f;
    __syncthreads();

    int ir0 = strip*8 - 1;
    for (int i = tid; i < 32*560; i += 256) {
        int cc2 = i / 560; int rem = i - cc2*560;
        int r = rem / 56;  int col = rem - r*56;
        int ir = ir0 + r;
        if (ir >= 0 && ir < 56)
            xs[cc2*CHS + r*58 + col + 1] =
                x[((size_t)(b*CC + cglob + cc2))*LL + ir*56 + col];
    }
    __syncthreads();

    // branch 0 (stride 1)
    {
        float wq[9];
#pragma unroll
        for (int t = 0; t < 9; t++) wq[t] = dwk[t*CC + c];
        int orow = strip*8 + w;
        const float* r0 = &xs[lane*CHS + w*58];
        const float* r1 = r0 + 58;
        const float* r2 = r0 + 116;
        bf16* outp = g_yq + ((size_t)b*LL + orow*56)*CC + c;
        float s0 = 0.f, s1 = 0.f;
        float a0 = r0[0], a1 = r0[1];
        float b0 = r1[0], b1 = r1[1];
        float c0 = r2[0], c1 = r2[1];
        for (int col = 0; col < 56; col++) {
            float a2 = r0[col+2], b2 = r1[col+2], c2 = r2[col+2];
            float v = wq[0]*a0 + wq[1]*a1 + wq[2]*a2
                    + wq[3]*b0 + wq[4]*b1 + wq[5]*b2
                    + wq[6]*c0 + wq[7]*c1 + wq[8]*c2;
            bf16 h = __float2bfloat16(v);
            float vb = __bfloat162float(h);
            outp[(size_t)col*CC] = h;
            s0 += vb; s1 += vb*vb;
            a0 = a1; a1 = a2; b0 = b1; b1 = b2; c0 = c1; c1 = c2;
        }
        atomicAdd(&bacc[(0*32+lane)*2+0], s0);
        atomicAdd(&bacc[(0*32+lane)*2+1], s1);
    }
    // branches 1,2 (stride 2)
    {
        int br = 1 + (w >> 2);
        int rr = w & 3;
        float wt[9];
#pragma unroll
        for (int t = 0; t < 9; t++) wt[t] = dwk[(br*9 + t)*CC + c];
        int orow = strip*4 + rr;
        const float* r0 = &xs[lane*CHS + (2*rr)*58];
        const float* r1 = r0 + 58;
        const float* r2 = r0 + 116;
        bf16* outp = ((br == 1) ? g_yk : g_yv) + ((size_t)b*NK + orow*28)*CC + c;
        float s0 = 0.f, s1 = 0.f;
        for (int ocol = 0; ocol < 28; ocol++) {
            int ic = 2*ocol;
            float v = wt[0]*r0[ic] + wt[1]*r0[ic+1] + wt[2]*r0[ic+2]
                    + wt[3]*r1[ic] + wt[4]*r1[ic+1] + wt[5]*r1[ic+2]
                    + wt[6]*r2[ic] + wt[7]*r2[ic+1] + wt[8]*r2[ic+2];
            bf16 h = __float2bfloat16(v);
            float vb = __bfloat162float(h);
            outp[(size_t)ocol*CC] = h;
            s0 += vb; s1 += vb*vb;
        }
        atomicAdd(&bacc[(br*32+lane)*2+0], s0);
        atomicAdd(&bacc[(br*32+lane)*2+1], s1);
    }
    __syncthreads();
    if (tid < 32) {
        for (int br = 0; br < 3; br++) {
            atomicAdd(&g_stats[(br*CC + cglob + tid)*2 + 0], bacc[(br*32+tid)*2+0]);
            atomicAdd(&g_stats[(br*CC + cglob + tid)*2 + 1], bacc[(br*32+tid)*2+1]);
        }
    }
}

// BN fold + weight fold fused.
__global__ void wfold_kernel(const float* __restrict__ bn2g,
                             const float* __restrict__ bn2b,
                             const float* __restrict__ pww,
                             const float* __restrict__ pwb) {
    int o = blockIdx.x, br = blockIdx.y;
    int c = threadIdx.x;
    float cnt = (br == 0) ? (float)(BB*(size_t)LL) : (float)(BB*(size_t)NK);
    float s  = g_stats[(br*CC + c)*2 + 0];
    float s2 = g_stats[(br*CC + c)*2 + 1];
    float mu = s / cnt;
    float var = s2 / cnt - mu*mu;
    float rstd = rsqrtf(var + 1e-5f);
    float sc = bn2g[br*CC + c] * rstd;
    float sh = bn2b[br*CC + c] - mu*sc;

    float w = pww[((size_t)br*CC + o)*CC + c];
    g_Wp[((size_t)br*CC + o)*CC + c] = __float2bfloat16(w * sc);
    float v = w * sh;
    __shared__ float red[12];
#pragma unroll
    for (int off = 16; off > 0; off >>= 1) v += __shfl_down_sync(0xffffffffu, v, off);
    if ((c & 31) == 0) red[c >> 5] = v;
    __syncthreads();
    if (c == 0) {
        float t = 0.f;
        for (int i = 0; i < 12; i++) t += red[i];
        g_bp[br*CC + o] = pwb[br*CC + o] + t;
    }
}

// -------- bf16 mma.sync m16n8k16 GEMM + bias + exact GELU -------------------
// Independent 128x128 tiles; 64-wide k-stages (6 total), 3-stage cp.async ring,
// ldmatrix fragment loads, one sync per stage (6 syncs).
// Flat grid 3528 with n-tile fastest (bx = mt*3 + nt) -> Y m-block L2 reuse.
#define GELW 72                 // smem row stride in bf16 elements (144 bytes)
#define STG_E (2*128*GELW)      // elements per stage (A rows 0-127, B rows 128-255)
#define STG_B (STG_E*2)         // bytes per stage (36 KB)
__global__ void __launch_bounds__(256, 2)
gemm_mma_kernel() {
    int bx = blockIdx.x;
    int mtg = bx / 3, nt = bx - mtg*3;
    int branch, mt;
    if (mtg < 784)      { branch = 0; mt = mtg; }
    else if (mtg < 980) { branch = 1; mt = mtg - 784; }
    else                { branch = 2; mt = mtg - 980; }
    const bf16* Y   = (branch == 0) ? g_yq   : (branch == 1) ? g_yk   : g_yv;
    bf16*       act = (branch == 0) ? g_qact : (branch == 1) ? g_kact : g_vact;
    const bf16* W   = g_Wp + (size_t)branch*CC*CC;
    const float* bp = g_bp + branch*CC;
    int m0 = mt * 128;
    int n0 = nt * 128;

    extern __shared__ bf16 smb[];        // [3][2][128][GELW]
    uint32_t sA = smem_u32(smb);

    int tid = threadIdx.x;
    int warp = tid >> 5, lane = tid & 31;
    int wm = warp >> 2, wn = warp & 3;
    int grp = lane >> 2, qu = lane & 3;

    float cfr[4][4][4];
#pragma unroll
    for (int mi = 0; mi < 4; mi++)
#pragma unroll
        for (int ni = 0; ni < 4; ni++)
#pragma unroll
            for (int r = 0; r < 4; r++) cfr[mi][ni][r] = 0.f;

    // cp.async mapping: 2048 16B-chunks per stage (256 rows x 8 chunks)
    int lrow = tid >> 3;          // rows 0..31 base (x8 pages below)
    int lch  = (tid & 7) * 8;     // element offset (8 bf16 = 16 B)

    // ldmatrix per-thread base addresses (byte offsets into stage 0)
    uint32_t aAddr[4];
#pragma unroll
    for (int mi = 0; mi < 4; mi++)
        aAddr[mi] = sA + (uint32_t)(((wm*64 + mi*16 + (lane & 15))*GELW
                                    + (lane >> 4)*8) * 2);
    uint32_t bAddr[2];
#pragma unroll
    for (int np = 0; np < 2; np++)
        bAddr[np] = sA + (uint32_t)(((128 + wn*32 + np*16 + (lane >> 4)*8
                                     + (lane & 7))*GELW
                                    + ((lane >> 3) & 1)*8) * 2);

#define LOAD_STAGE(buf, k0) do { \
    uint32_t base_ = sA + (uint32_t)(buf)*STG_B; \
    _Pragma("unroll") \
    for (int p = 0; p < 4; p++) { \
        int row = lrow + p*32; \
        CP_ASYNC16(base_ + (uint32_t)(row*GELW + lch)*2, \
                   Y + (size_t)(m0+row)*CC + (k0) + lch); \
        CP_ASYNC16(base_ + (uint32_t)((128 + row)*GELW + lch)*2, \
                   W + (size_t)(n0+row)*CC + (k0) + lch); \
    } \
    CP_COMMIT(); \
} while (0)

    LOAD_STAGE(0, 0);
    LOAD_STAGE(1, 64);

    for (int ks = 0; ks < 6; ks++) {
        int buf = ks % 3;
        if (ks < 5) { CP_WAITN(1); } else { CP_WAITN(0); }
        __syncthreads();
        if (ks + 2 < 6) LOAD_STAGE((ks+2) % 3, (ks+2)*64);

        uint32_t boff = (uint32_t)buf * STG_B;
#pragma unroll
        for (int t = 0; t < 4; t++) {
            uint32_t koff = boff + t*32;     // t*16 elems * 2 bytes
            uint32_t a[4][4], bq[4][2];
#pragma unroll
            for (int mi = 0; mi < 4; mi++)
                LDSM_X4(a[mi][0], a[mi][1], a[mi][2], a[mi][3], aAddr[mi] + koff);
#pragma unroll
            for (int np = 0; np < 2; np++)
                LDSM_X4(bq[2*np][0], bq[2*np][1], bq[2*np+1][0], bq[2*np+1][1],
                        bAddr[np] + koff);
#pragma unroll
            for (int mi = 0; mi < 4; mi++)
#pragma unroll
                for (int ni = 0; ni < 4; ni++)
                    asm volatile(
                        "mma.sync.aligned.m16n8k16.row.col.f32.bf16.bf16.f32 "
                        "{%0,%1,%2,%3}, {%4,%5,%6,%7}, {%8,%9}, {%0,%1,%2,%3};"
                        : "+f"(cfr[mi][ni][0]), "+f"(cfr[mi][ni][1]),
                          "+f"(cfr[mi][ni][2]), "+f"(cfr[mi][ni][3])
                        : "r"(a[mi][0]), "r"(a[mi][1]), "r"(a[mi][2]), "r"(a[mi][3]),
                          "r"(bq[ni][0]), "r"(bq[ni][1]));
        }
    }

    // epilogue: bias + exact gelu -> bf16 stores
#pragma unroll
    for (int ni = 0; ni < 4; ni++) {
        int col = n0 + wn*32 + ni*8 + qu*2;
        float b0 = bp[col], b1 = bp[col+1];
#pragma unroll
        for (int mi = 0; mi < 4; mi++) {
            int row = m0 + wm*64 + mi*16 + grp;
            float v0 = cfr[mi][ni][0] + b0; v0 = v0 * normcdff(v0);
            float v1 = cfr[mi][ni][1] + b1; v1 = v1 * normcdff(v1);
            *reinterpret_cast<__nv_bfloat162*>(&act[(size_t)row*CC + col]) =
                __floats2bfloat162_rn(v0, v1);
            float v2 = cfr[mi][ni][2] + b0; v2 = v2 * normcdff(v2);
            float v3 = cfr[mi][ni][3] + b1; v3 = v3 * normcdff(v3);
            *reinterpret_cast<__nv_bfloat162*>(&act[(size_t)(row+8)*CC + col]) =
                __floats2bfloat162_rn(v2, v3);
        }
    }
#undef LOAD_STAGE
}

// kv[b,h,d,e] = sum_n softmax_n(k)[n,d] * v[n,e]; k/v in bf16.
__global__ void kv_kernel() {
    int bh = blockIdx.x;
    int b = bh / HEADS, h = bh % HEADS;
    const bf16* kp = g_kact + (size_t)b*NK*CC + h*DH;
    const bf16* vp = g_vact + (size_t)b*NK*CC + h*DH;
    int tid = threadIdx.x;
    __shared__ float maxd[DH], Zd[DH];
    __shared__ float redm[8][DH], redz[8][DH];
    int d = tid & 31, r = tid >> 5;

    float m = -INFINITY, z = 0.f;
    for (int n = r; n < NK; n += 8) {
        float kvl = __bfloat162float(kp[(size_t)n*CC + d]);
        if (kvl > m) { z = z * expf(m - kvl) + 1.f; m = kvl; }
        else         { z += expf(kvl - m); }
    }
    redm[r][d] = m; redz[r][d] = z;
    __syncthreads();
    if (r == 0) {
        float M = redm[0][d];
        for (int i = 1; i < 8; i++) M = fmaxf(M, redm[i][d]);
        float Z = 0.f;
        for (int i = 0; i < 8; i++) Z += redz[i][d] * expf(redm[i][d] - M);
        maxd[d] = M; Zd[d] = Z;
    }

    __shared__ float ke[64][DH], ve[64][DH];
    float acc[4] = {0.f, 0.f, 0.f, 0.f};
    int dd = tid >> 3;
    int e0 = (tid & 7) * 4;
    for (int t0 = 0; t0 < NK; t0 += 64) {
        int rows = min(64, NK - t0);
        __syncthreads();
        for (int idx = tid; idx < rows*DH; idx += 256) {
            int rr = idx >> 5, c2 = idx & 31;
            ke[rr][c2] = expf(__bfloat162float(kp[(size_t)(t0+rr)*CC + c2]) - maxd[c2]);
            ve[rr][c2] = __bfloat162float(vp[(size_t)(t0+rr)*CC + c2]);
        }
        __syncthreads();
        for (int rr = 0; rr < rows; rr++) {
            float kk = ke[rr][dd];
            float4 vv = *reinterpret_cast<float4*>(&ve[rr][e0]);
            acc[0] += kk*vv.x; acc[1] += kk*vv.y;
            acc[2] += kk*vv.z; acc[3] += kk*vv.w;
        }
    }
    float rz = 1.f / Zd[dd];
    float* o = g_kv + ((size_t)bh*DH + dd)*DH + e0;
    o[0] = acc[0]*rz; o[1] = acc[1]*rz; o[2] = acc[2]*rz; o[3] = acc[3]*rz;
}

// q-softmax + att matvec + weighted residual -> fp16 y + BN1 stats.
__global__ void att_kernel(const float* __restrict__ x,
                           const float* __restrict__ addw) {
    extern __shared__ float smem[];
    float* kvs = smem;                                    // 12*32*32 f32
    __half* att_s = reinterpret_cast<__half*>(smem + HEADS*DH*DH); // [CC][32] fp16
    int b  = blockIdx.x;
    int n0 = blockIdx.y * 32;
    int tid = threadIdx.x;
    int h = tid >> 5, tok = tid & 31;

    {
        const float* kvp = g_kv + ((size_t)b*HEADS + h)*DH*DH;
        for (int i = tok; i < DH*DH; i += 32) kvs[h*DH*DH + i] = kvp[i];
    }
    __syncthreads();

    float qs[DH];
    {
        const bf16* qp = g_qact + ((size_t)b*LL + n0 + tok)*CC + h*DH;
        const uint4* qp4 = reinterpret_cast<const uint4*>(qp);
        float m = -INFINITY;
#pragma unroll
        for (int i = 0; i < 4; i++) {
            uint4 u = qp4[i];
            const __nv_bfloat162* pv = reinterpret_cast<const __nv_bfloat162*>(&u);
#pragma unroll
            for (int j = 0; j < 4; j++) {
                float2 v = __bfloat1622float2(pv[j]);
                qs[i*8 + j*2 + 0] = v.x;
                qs[i*8 + j*2 + 1] = v.y;
            }
        }
#pragma unroll
        for (int d2 = 0; d2 < DH; d2++) m = fmaxf(m, qs[d2]);
        float Z = 0.f;
#pragma unroll
        for (int d2 = 0; d2 < DH; d2++) { qs[d2] = expf(qs[d2]-m); Z += qs[d2]; }
        float rz = 1.f / Z;
#pragma unroll
        for (int d2 = 0; d2 < DH; d2++) qs[d2] *= rz;
    }
    float acc[DH];
#pragma unroll
    for (int e = 0; e < DH; e++) acc[e] = 0.f;
    const float4* kv4 = reinterpret_cast<const float4*>(kvs + h*DH*DH);
#pragma unroll
    for (int d2 = 0; d2 < DH; d2++) {
        float qd = qs[d2];
#pragma unroll
        for (int e4 = 0; e4 < 8; e4++) {
            float4 v = kv4[d2*8 + e4];
            acc[e4*4+0] += qd*v.x; acc[e4*4+1] += qd*v.y;
            acc[e4*4+2] += qd*v.z; acc[e4*4+3] += qd*v.w;
        }
    }
#pragma unroll
    for (int e = 0; e < DH; e++) att_s[(h*DH + e)*32 + tok] = __float2half_rn(acc[e]);
    __syncthreads();

    float w0 = fmaxf(addw[0], 0.f), w1 = fmaxf(addw[1], 0.f);
    float inv = 1.f / (w0 + w1 + 1e-12f);
    w0 *= inv; w1 *= inv;
    int g = tid >> 5, lane = tid & 31;
    for (int c = g; c < CC; c += 12) {
        float xv = x[((size_t)b*CC + c)*LL + n0 + lane];
        float av = __half2float(att_s[c*32 + lane]);
        float y = w0*av + w1*xv;
        __half hy = __float2half_rn(y);
        float yq = __half2float(hy);
        g_yh[((size_t)b*CC + c)*LL + n0 + lane] = hy;
        float s = yq, s2 = yq*yq;
#pragma unroll
        for (int off = 16; off > 0; off >>= 1) {
            s  += __shfl_down_sync(0xffffffffu, s, off);
            s2 += __shfl_down_sync(0xffffffffu, s2, off);
        }
        if (lane == 0) {
            atomicAdd(&g_bn1s[c*2 + 0], s);
            atomicAdd(&g_bn1s[c*2 + 1], s2);
        }
    }
}

__global__ void bn1_final_kernel() {
    int c = threadIdx.x;
    float cnt = (float)((size_t)BB*LL);
    float mu = g_bn1s[c*2] / cnt;
    float var = g_bn1s[c*2+1] / cnt - mu*mu;
    g_bn1f[c*2]   = mu;
    g_bn1f[c*2+1] = rsqrtf(var + 1e-5f);
}

// read fp16 y, normalize, write fp32 out
__global__ void bn1_apply_kernel(const float* __restrict__ g1,
                                 const float* __restrict__ b1,
                                 float* __restrict__ out) {
    const size_t n4 = (size_t)BB*CC*LL/4;
    const int L4 = LL/4;
    const uint2* y4 = reinterpret_cast<const uint2*>(g_yh);
    float4* o4 = reinterpret_cast<float4*>(out);
    for (size_t i = (size_t)blockIdx.x*blockDim.x + threadIdx.x; i < n4;
         i += (size_t)gridDim.x*blockDim.x) {
        int c = (int)((i / L4) % CC);
        float mu = g_bn1f[c*2], rstd = g_bn1f[c*2+1];
        float sc = rstd * g1[c];
        float sh = b1[c] - mu*sc;
        uint2 u = y4[i];
        const __half2* hp = reinterpret_cast<const __half2*>(&u);
        float2 p0 = __half22float2(hp[0]);
        float2 p1 = __half22float2(hp[1]);
        float4 v;
        v.x = p0.x*sc + sh; v.y = p0.y*sc + sh;
        v.z = p1.x*sc + sh; v.w = p1.y*sc + sh;
        o4[i] = v;
    }
}

// ---------------- host-side launch ------------------------------------------
static bool g_init = false;

extern "C" void kernel_launch(void* const* d_in, const int* in_sizes, int n_in,
                              void* d_out, int out_size) {
    const float* x    = (const float*)d_in[0];
    const float* dwk  = (const float*)d_in[1];
    const float* bn2g = (const float*)d_in[2];
    const float* bn2b = (const float*)d_in[3];
    const float* pww  = (const float*)d_in[4];
    const float* pwb  = (const float*)d_in[5];
    const float* addw = (const float*)d_in[6];
    const float* bn1g = (const float*)d_in[7];
    const float* bn1b = (const float*)d_in[8];
    float* out = (float*)d_out;

    const int dw_smem   = 32*CHS*(int)sizeof(float);
    const int gemm_smem = 3*STG_B;                     // 108 KB
    const int att_smem  = HEADS*DH*DH*(int)sizeof(float) + CC*32*(int)sizeof(__half);

    if (!g_init) {
        cudaFuncSetAttribute(dwconv_fused,
            cudaFuncAttributeMaxDynamicSharedMemorySize, dw_smem);
        cudaFuncSetAttribute(gemm_mma_kernel,
            cudaFuncAttributeMaxDynamicSharedMemorySize, gemm_smem);
        cudaFuncSetAttribute(att_kernel,
            cudaFuncAttributeMaxDynamicSharedMemorySize, att_smem);
        g_init = true;
    }

    zero_stats_kernel<<<(3*CC*2 + 255)/256, 256>>>();
    dwconv_fused<<<dim3(7, 12, BB), 256, dw_smem>>>(x, dwk);
    wfold_kernel<<<dim3(CC, 3), CC>>>(bn2g, bn2b, pww, pwb);
    gemm_mma_kernel<<<3528, 256, gemm_smem>>>();
    kv_kernel<<<BB*HEADS, 256>>>();
    att_kernel<<<dim3(BB, LL/32), 384, att_smem>>>(x, addw);
    bn1_final_kernel<<<1, CC>>>();
    bn1_apply_kernel<<<2048, 256>>>(bn1g, bn1b, out);
}

// round 15
// speedup vs baseline: 1.0227x; 1.0227x over previous
#include <cuda_runtime.h>
#include <cuda.h>
#include <cuda_bf16.h>
#include <cuda_fp16.h>
#include <math.h>
#include <stdint.h>

#define BB 32
#define CC 384
#define LL 3136
#define HIMG 56
#define HEADS 12
#define DH 32
#define NK 784

typedef __nv_bfloat16 bf16;

// ---------------- scratch (device globals; no allocation allowed) ----------
__device__ __align__(16) bf16 g_yq[(size_t)BB*LL*CC];   // dwconv out (bf16), [b,n,c]
__device__ __align__(16) bf16 g_yk[(size_t)BB*NK*CC];
__device__ __align__(16) bf16 g_yv[(size_t)BB*NK*CC];
__device__ float g_stats[3*CC*2];          // zero-init at load; re-zeroed in gemm
__device__ __align__(16) bf16 g_Wp[(size_t)3*CC*CC];    // BN-folded pointwise weights
__device__ float g_bp[3*CC];
__device__ __align__(16) bf16 g_qact[(size_t)BB*LL*CC]; // q act bf16 [b,n,c]
__device__ __align__(16) bf16 g_kact[(size_t)BB*NK*CC]; // k act bf16
__device__ __align__(16) bf16 g_vact[(size_t)BB*NK*CC]; // v act bf16
__device__ float g_kv[(size_t)BB*HEADS*DH*DH];
__device__ __align__(16) __half g_yh[(size_t)BB*CC*LL]; // pre-BN1 y (fp16), [b,c,l]
__device__ float g_bn1s[CC*2];             // zero-init; re-zeroed in bn1_final
__device__ float g_bn1f[CC*2];

// ---------------- helpers ---------------------------------------------------
__device__ __forceinline__ uint32_t smem_u32(const void* p) {
    uint32_t a;
    asm("{ .reg .u64 t; cvta.to.shared.u64 t, %1; cvt.u32.u64 %0, t; }" : "=r"(a) : "l"(p));
    return a;
}
#define CP_ASYNC16(dst, src) \
    asm volatile("cp.async.cg.shared.global [%0], [%1], 16;" :: "r"(dst), "l"(src))
#define CP_COMMIT() asm volatile("cp.async.commit_group;" ::: "memory")
#define CP_WAITN(n) asm volatile("cp.async.wait_group %0;" :: "n"(n) : "memory")
#define LDSM_X4(r0, r1, r2, r3, addr) \
    asm volatile("ldmatrix.sync.aligned.m8n8.x4.shared.b16 {%0,%1,%2,%3}, [%4];" \
        : "=r"(r0), "=r"(r1), "=r"(r2), "=r"(r3) : "r"(addr))

// ---------------- kernels --------------------------------------------------

// Fused depthwise 3x3 (3 branches), transposed bf16 output [b,n,c], BN stats.
#define CHS 581
__global__ void dwconv_fused(const float* __restrict__ x,
                             const float* __restrict__ dwk) {
    extern __shared__ float xs[];
    __shared__ float bacc[3*32*2];
    int strip = blockIdx.x, cg = blockIdx.y, b = blockIdx.z;
    int tid = threadIdx.x;
    int w = tid >> 5, lane = tid & 31;
    int cglob = cg * 32;
    int c = cglob + lane;

    if (tid < 192) bacc[tid] = 0.f;
    for (int i = tid; i < 32*CHS; i += 256) xs[i] = 0.f;
    __syncthreads();

    int ir0 = strip*8 - 1;
    for (int i = tid; i < 32*560; i += 256) {
        int cc2 = i / 560; int rem = i - cc2*560;
        int r = rem / 56;  int col = rem - r*56;
        int ir = ir0 + r;
        if (ir >= 0 && ir < 56)
            xs[cc2*CHS + r*58 + col + 1] =
                x[((size_t)(b*CC + cglob + cc2))*LL + ir*56 + col];
    }
    __syncthreads();

    // branch 0 (stride 1)
    {
        float wq[9];
#pragma unroll
        for (int t = 0; t < 9; t++) wq[t] = dwk[t*CC + c];
        int orow = strip*8 + w;
        const float* r0 = &xs[lane*CHS + w*58];
        const float* r1 = r0 + 58;
        const float* r2 = r0 + 116;
        bf16* outp = g_yq + ((size_t)b*LL + orow*56)*CC + c;
        float s0 = 0.f, s1 = 0.f;
        float a0 = r0[0], a1 = r0[1];
        float b0 = r1[0], b1 = r1[1];
        float c0 = r2[0], c1 = r2[1];
        for (int col = 0; col < 56; col++) {
            float a2 = r0[col+2], b2 = r1[col+2], c2 = r2[col+2];
            float v = wq[0]*a0 + wq[1]*a1 + wq[2]*a2
                    + wq[3]*b0 + wq[4]*b1 + wq[5]*b2
                    + wq[6]*c0 + wq[7]*c1 + wq[8]*c2;
            bf16 h = __float2bfloat16(v);
            float vb = __bfloat162float(h);
            outp[(size_t)col*CC] = h;
            s0 += vb; s1 += vb*vb;
            a0 = a1; a1 = a2; b0 = b1; b1 = b2; c0 = c1; c1 = c2;
        }
        atomicAdd(&bacc[(0*32+lane)*2+0], s0);
        atomicAdd(&bacc[(0*32+lane)*2+1], s1);
    }
    // branches 1,2 (stride 2)
    {
        int br = 1 + (w >> 2);
        int rr = w & 3;
        float wt[9];
#pragma unroll
        for (int t = 0; t < 9; t++) wt[t] = dwk[(br*9 + t)*CC + c];
        int orow = strip*4 + rr;
        const float* r0 = &xs[lane*CHS + (2*rr)*58];
        const float* r1 = r0 + 58;
        const float* r2 = r0 + 116;
        bf16* outp = ((br == 1) ? g_yk : g_yv) + ((size_t)b*NK + orow*28)*CC + c;
        float s0 = 0.f, s1 = 0.f;
        for (int ocol = 0; ocol < 28; ocol++) {
            int ic = 2*ocol;
            float v = wt[0]*r0[ic] + wt[1]*r0[ic+1] + wt[2]*r0[ic+2]
                    + wt[3]*r1[ic] + wt[4]*r1[ic+1] + wt[5]*r1[ic+2]
                    + wt[6]*r2[ic] + wt[7]*r2[ic+1] + wt[8]*r2[ic+2];
            bf16 h = __float2bfloat16(v);
            float vb = __bfloat162float(h);
            outp[(size_t)ocol*CC] = h;
            s0 += vb; s1 += vb*vb;
        }
        atomicAdd(&bacc[(br*32+lane)*2+0], s0);
        atomicAdd(&bacc[(br*32+lane)*2+1], s1);
    }
    __syncthreads();
    if (tid < 32) {
        for (int br = 0; br < 3; br++) {
            atomicAdd(&g_stats[(br*CC + cglob + tid)*2 + 0], bacc[(br*32+tid)*2+0]);
            atomicAdd(&g_stats[(br*CC + cglob + tid)*2 + 1], bacc[(br*32+tid)*2+1]);
        }
    }
}

// BN fold + weight fold fused.
__global__ void wfold_kernel(const float* __restrict__ bn2g,
                             const float* __restrict__ bn2b,
                             const float* __restrict__ pww,
                             const float* __restrict__ pwb) {
    int o = blockIdx.x, br = blockIdx.y;
    int c = threadIdx.x;
    float cnt = (br == 0) ? (float)(BB*(size_t)LL) : (float)(BB*(size_t)NK);
    float s  = g_stats[(br*CC + c)*2 + 0];
    float s2 = g_stats[(br*CC + c)*2 + 1];
    float mu = s / cnt;
    float var = s2 / cnt - mu*mu;
    float rstd = rsqrtf(var + 1e-5f);
    float sc = bn2g[br*CC + c] * rstd;
    float sh = bn2b[br*CC + c] - mu*sc;

    float w = pww[((size_t)br*CC + o)*CC + c];
    g_Wp[((size_t)br*CC + o)*CC + c] = __float2bfloat16(w * sc);
    float v = w * sh;
    __shared__ float red[12];
#pragma unroll
    for (int off = 16; off > 0; off >>= 1) v += __shfl_down_sync(0xffffffffu, v, off);
    if ((c & 31) == 0) red[c >> 5] = v;
    __syncthreads();
    if (c == 0) {
        float t = 0.f;
        for (int i = 0; i < 12; i++) t += red[i];
        g_bp[br*CC + o] = pwb[br*CC + o] + t;
    }
}

// -------- bf16 mma.sync m16n8k16 GEMM + bias + exact GELU -------------------
// CTA tile 64x128 (M x N), 8 warps (4m x 2n), warp tile 16x64.
// 4-stage cp.async ring of 32-wide k-stages, ldmatrix fragment loads.
// 3 CTAs/SM (24 warps). Flat grid 7056 with n-tile fastest -> Y L2 reuse.
#define GEL 40                 // smem row stride in bf16 elements (80 bytes)
#define STG_E (192*GEL)        // elements per stage (A rows 0-63, B rows 64-191)
#define STG_B (STG_E*2)        // bytes per stage (15360)
__global__ void __launch_bounds__(256, 3)
gemm_mma_kernel() {
    int bx = blockIdx.x;
    int tid = threadIdx.x;
    if (bx == 0) {             // re-zero dwconv stats for the next replay
        for (int i = tid; i < 3*CC*2; i += 256) g_stats[i] = 0.f;
    }
    int mtg = bx / 3, nt = bx - mtg*3;
    int branch, mt;
    if (mtg < 1568)      { branch = 0; mt = mtg; }
    else if (mtg < 1960) { branch = 1; mt = mtg - 1568; }
    else                 { branch = 2; mt = mtg - 1960; }
    const bf16* Y   = (branch == 0) ? g_yq   : (branch == 1) ? g_yk   : g_yv;
    bf16*       act = (branch == 0) ? g_qact : (branch == 1) ? g_kact : g_vact;
    const bf16* W   = g_Wp + (size_t)branch*CC*CC;
    const float* bp = g_bp + branch*CC;
    int m0 = mt * 64;
    int n0 = nt * 128;

    extern __shared__ bf16 smb[];        // [4][192][GEL]
    uint32_t sA = smem_u32(smb);

    int warp = tid >> 5, lane = tid & 31;
    int wm = warp >> 1, wn = warp & 1;
    int grp = lane >> 2, qu = lane & 3;

    float cfr[8][4];
#pragma unroll
    for (int ni = 0; ni < 8; ni++)
#pragma unroll
        for (int r = 0; r < 4; r++) cfr[ni][r] = 0.f;

    // cp.async mapping: 768 16B-chunks per stage; thread handles 3 (p=0:A, p=1,2:B)
    int lrow = tid >> 2;          // 0..63
    int lch  = (tid & 3) * 8;     // element offset (8 bf16 = 16 B)

    // ldmatrix per-thread base addresses (byte offsets into stage 0)
    uint32_t aAddr = sA + (uint32_t)(((wm*16 + (lane & 15))*GEL
                                     + (lane >> 4)*8) * 2);
    uint32_t bAddr[4];
#pragma unroll
    for (int np = 0; np < 4; np++)
        bAddr[np] = sA + (uint32_t)(((64 + wn*64 + np*16 + (lane >> 4)*8
                                     + (lane & 7))*GEL
                                    + ((lane >> 3) & 1)*8) * 2);

#define LOAD_STAGE(buf, k0) do { \
    uint32_t base_ = sA + (uint32_t)(buf)*STG_B; \
    CP_ASYNC16(base_ + (uint32_t)(lrow*GEL + lch)*2, \
               Y + (size_t)(m0+lrow)*CC + (k0) + lch); \
    _Pragma("unroll") \
    for (int p = 0; p < 2; p++) { \
        int row = lrow + p*64; \
        CP_ASYNC16(base_ + (uint32_t)((64 + row)*GEL + lch)*2, \
                   W + (size_t)(n0+row)*CC + (k0) + lch); \
    } \
    CP_COMMIT(); \
} while (0)

    LOAD_STAGE(0, 0);
    LOAD_STAGE(1, 32);
    LOAD_STAGE(2, 64);

    for (int ks = 0; ks < 12; ks++) {
        int buf = ks & 3;
        if (ks <= 9)       { CP_WAITN(2); }
        else if (ks == 10) { CP_WAITN(1); }
        else               { CP_WAITN(0); }
        __syncthreads();
        if (ks + 3 < 12) LOAD_STAGE((ks+3) & 3, (ks+3)*32);

        uint32_t boff = (uint32_t)buf * STG_B;
#pragma unroll
        for (int t = 0; t < 2; t++) {
            uint32_t koff = boff + t*32;     // t*16 elems * 2 bytes
            uint32_t a[4], bq[8][2];
            LDSM_X4(a[0], a[1], a[2], a[3], aAddr + koff);
#pragma unroll
            for (int np = 0; np < 4; np++)
                LDSM_X4(bq[2*np][0], bq[2*np][1], bq[2*np+1][0], bq[2*np+1][1],
                        bAddr[np] + koff);
#pragma unroll
            for (int ni = 0; ni < 8; ni++)
                asm volatile(
                    "mma.sync.aligned.m16n8k16.row.col.f32.bf16.bf16.f32 "
                    "{%0,%1,%2,%3}, {%4,%5,%6,%7}, {%8,%9}, {%0,%1,%2,%3};"
                    : "+f"(cfr[ni][0]), "+f"(cfr[ni][1]),
                      "+f"(cfr[ni][2]), "+f"(cfr[ni][3])
                    : "r"(a[0]), "r"(a[1]), "r"(a[2]), "r"(a[3]),
                      "r"(bq[ni][0]), "r"(bq[ni][1]));
        }
    }

    // epilogue: bias + exact gelu -> bf16 stores
#pragma unroll
    for (int ni = 0; ni < 8; ni++) {
        int col = n0 + wn*64 + ni*8 + qu*2;
        float b0 = bp[col], b1 = bp[col+1];
        int row = m0 + wm*16 + grp;
        float v0 = cfr[ni][0] + b0; v0 = v0 * normcdff(v0);
        float v1 = cfr[ni][1] + b1; v1 = v1 * normcdff(v1);
        *reinterpret_cast<__nv_bfloat162*>(&act[(size_t)row*CC + col]) =
            __floats2bfloat162_rn(v0, v1);
        float v2 = cfr[ni][2] + b0; v2 = v2 * normcdff(v2);
        float v3 = cfr[ni][3] + b1; v3 = v3 * normcdff(v3);
        *reinterpret_cast<__nv_bfloat162*>(&act[(size_t)(row+8)*CC + col]) =
            __floats2bfloat162_rn(v2, v3);
    }
#undef LOAD_STAGE
}

// kv[b,h,d,e] = sum_n softmax_n(k)[n,d] * v[n,e]; k/v in bf16.
__global__ void kv_kernel() {
    int bh = blockIdx.x;
    int b = bh / HEADS, h = bh % HEADS;
    const bf16* kp = g_kact + (size_t)b*NK*CC + h*DH;
    const bf16* vp = g_vact + (size_t)b*NK*CC + h*DH;
    int tid = threadIdx.x;
    __shared__ float maxd[DH], Zd[DH];
    __shared__ float redm[8][DH], redz[8][DH];
    int d = tid & 31, r = tid >> 5;

    float m = -INFINITY, z = 0.f;
    for (int n = r; n < NK; n += 8) {
        float kvl = __bfloat162float(kp[(size_t)n*CC + d]);
        if (kvl > m) { z = z * expf(m - kvl) + 1.f; m = kvl; }
        else         { z += expf(kvl - m); }
    }
    redm[r][d] = m; redz[r][d] = z;
    __syncthreads();
    if (r == 0) {
        float M = redm[0][d];
        for (int i = 1; i < 8; i++) M = fmaxf(M, redm[i][d]);
        float Z = 0.f;
        for (int i = 0; i < 8; i++) Z += redz[i][d] * expf(redm[i][d] - M);
        maxd[d] = M; Zd[d] = Z;
    }

    __shared__ float ke[64][DH], ve[64][DH];
    float acc[4] = {0.f, 0.f, 0.f, 0.f};
    int dd = tid >> 3;
    int e0 = (tid & 7) * 4;
    for (int t0 = 0; t0 < NK; t0 += 64) {
        int rows = min(64, NK - t0);
        __syncthreads();
        for (int idx = tid; idx < rows*DH; idx += 256) {
            int rr = idx >> 5, c2 = idx & 31;
            ke[rr][c2] = expf(__bfloat162float(kp[(size_t)(t0+rr)*CC + c2]) - maxd[c2]);
            ve[rr][c2] = __bfloat162float(vp[(size_t)(t0+rr)*CC + c2]);
        }
        __syncthreads();
        for (int rr = 0; rr < rows; rr++) {
            float kk = ke[rr][dd];
            float4 vv = *reinterpret_cast<float4*>(&ve[rr][e0]);
            acc[0] += kk*vv.x; acc[1] += kk*vv.y;
            acc[2] += kk*vv.z; acc[3] += kk*vv.w;
        }
    }
    float rz = 1.f / Zd[dd];
    float* o = g_kv + ((size_t)bh*DH + dd)*DH + e0;
    o[0] = acc[0]*rz; o[1] = acc[1]*rz; o[2] = acc[2]*rz; o[3] = acc[3]*rz;
}

// q-softmax + att matvec + weighted residual -> fp16 y + BN1 stats.
__global__ void att_kernel(const float* __restrict__ x,
                           const float* __restrict__ addw) {
    extern __shared__ float smem[];
    float* kvs = smem;                                    // 12*32*32 f32
    __half* att_s = reinterpret_cast<__half*>(smem + HEADS*DH*DH); // [CC][32] fp16
    int b  = blockIdx.x;
    int n0 = blockIdx.y * 32;
    int tid = threadIdx.x;
    int h = tid >> 5, tok = tid & 31;

    {
        const float* kvp = g_kv + ((size_t)b*HEADS + h)*DH*DH;
        for (int i = tok; i < DH*DH; i += 32) kvs[h*DH*DH + i] = kvp[i];
    }
    __syncthreads();

    float qs[DH];
    {
        const bf16* qp = g_qact + ((size_t)b*LL + n0 + tok)*CC + h*DH;
        const uint4* qp4 = reinterpret_cast<const uint4*>(qp);
        float m = -INFINITY;
#pragma unroll
        for (int i = 0; i < 4; i++) {
            uint4 u = qp4[i];
            const __nv_bfloat162* pv = reinterpret_cast<const __nv_bfloat162*>(&u);
#pragma unroll
            for (int j = 0; j < 4; j++) {
                float2 v = __bfloat1622float2(pv[j]);
                qs[i*8 + j*2 + 0] = v.x;
                qs[i*8 + j*2 + 1] = v.y;
            }
        }
#pragma unroll
        for (int d2 = 0; d2 < DH; d2++) m = fmaxf(m, qs[d2]);
        float Z = 0.f;
#pragma unroll
        for (int d2 = 0; d2 < DH; d2++) { qs[d2] = expf(qs[d2]-m); Z += qs[d2]; }
        float rz = 1.f / Z;
#pragma unroll
        for (int d2 = 0; d2 < DH; d2++) qs[d2] *= rz;
    }
    float acc[DH];
#pragma unroll
    for (int e = 0; e < DH; e++) acc[e] = 0.f;
    const float4* kv4 = reinterpret_cast<const float4*>(kvs + h*DH*DH);
#pragma unroll
    for (int d2 = 0; d2 < DH; d2++) {
        float qd = qs[d2];
#pragma unroll
        for (int e4 = 0; e4 < 8; e4++) {
            float4 v = kv4[d2*8 + e4];
            acc[e4*4+0] += qd*v.x; acc[e4*4+1] += qd*v.y;
            acc[e4*4+2] += qd*v.z; acc[e4*4+3] += qd*v.w;
        }
    }
#pragma unroll
    for (int e = 0; e < DH; e++) att_s[(h*DH + e)*32 + tok] = __float2half_rn(acc[e]);
    __syncthreads();

    float w0 = fmaxf(addw[0], 0.f), w1 = fmaxf(addw[1], 0.f);
    float inv = 1.f / (w0 + w1 + 1e-12f);
    w0 *= inv; w1 *= inv;
    int g = tid >> 5, lane = tid & 31;
    for (int c = g; c < CC; c += 12) {
        float xv = x[((size_t)b*CC + c)*LL + n0 + lane];
        float av = __half2float(att_s[c*32 + lane]);
        float y = w0*av + w1*xv;
        __half hy = __float2half_rn(y);
        float yq = __half2float(hy);
        g_yh[((size_t)b*CC + c)*LL + n0 + lane] = hy;
        float s = yq, s2 = yq*yq;
#pragma unroll
        for (int off = 16; off > 0; off >>= 1) {
            s  += __shfl_down_sync(0xffffffffu, s, off);
            s2 += __shfl_down_sync(0xffffffffu, s2, off);
        }
        if (lane == 0) {
            atomicAdd(&g_bn1s[c*2 + 0], s);
            atomicAdd(&g_bn1s[c*2 + 1], s2);
        }
    }
}

__global__ void bn1_final_kernel() {
    int c = threadIdx.x;
    float cnt = (float)((size_t)BB*LL);
    float s0 = g_bn1s[c*2], s1 = g_bn1s[c*2+1];
    float mu = s0 / cnt;
    float var = s1 / cnt - mu*mu;
    g_bn1f[c*2]   = mu;
    g_bn1f[c*2+1] = rsqrtf(var + 1e-5f);
    g_bn1s[c*2] = 0.f;          // re-zero for next replay
    g_bn1s[c*2+1] = 0.f;
}

// read fp16 y, normalize, write fp32 out
__global__ void bn1_apply_kernel(const float* __restrict__ g1,
                                 const float* __restrict__ b1,
                                 float* __restrict__ out) {
    const size_t n4 = (size_t)BB*CC*LL/4;
    const int L4 = LL/4;
    const uint2* y4 = reinterpret_cast<const uint2*>(g_yh);
    float4* o4 = reinterpret_cast<float4*>(out);
    for (size_t i = (size_t)blockIdx.x*blockDim.x + threadIdx.x; i < n4;
         i += (size_t)gridDim.x*blockDim.x) {
        int c = (int)((i / L4) % CC);
        float mu = g_bn1f[c*2], rstd = g_bn1f[c*2+1];
        float sc = rstd * g1[c];
        float sh = b1[c] - mu*sc;
        uint2 u = y4[i];
        const __half2* hp = reinterpret_cast<const __half2*>(&u);
        float2 p0 = __half22float2(hp[0]);
        float2 p1 = __half22float2(hp[1]);
        float4 v;
        v.x = p0.x*sc + sh; v.y = p0.y*sc + sh;
        v.z = p1.x*sc + sh; v.w = p1.y*sc + sh;
        o4[i] = v;
    }
}

// ---------------- host-side launch ------------------------------------------
static bool g_init = false;

extern "C" void kernel_launch(void* const* d_in, const int* in_sizes, int n_in,
                              void* d_out, int out_size) {
    const float* x    = (const float*)d_in[0];
    const float* dwk  = (const float*)d_in[1];
    const float* bn2g = (const float*)d_in[2];
    const float* bn2b = (const float*)d_in[3];
    const float* pww  = (const float*)d_in[4];
    const float* pwb  = (const float*)d_in[5];
    const float* addw = (const float*)d_in[6];
    const float* bn1g = (const float*)d_in[7];
    const float* bn1b = (const float*)d_in[8];
    float* out = (float*)d_out;

    const int dw_smem   = 32*CHS*(int)sizeof(float);
    const int gemm_smem = 4*STG_B;                     // 60 KB
    const int att_smem  = HEADS*DH*DH*(int)sizeof(float) + CC*32*(int)sizeof(__half);

    if (!g_init) {
        cudaFuncSetAttribute(dwconv_fused,
            cudaFuncAttributeMaxDynamicSharedMemorySize, dw_smem);
        cudaFuncSetAttribute(gemm_mma_kernel,
            cudaFuncAttributeMaxDynamicSharedMemorySize, gemm_smem);
        cudaFuncSetAttribute(att_kernel,
            cudaFuncAttributeMaxDynamicSharedMemorySize, att_smem);
        g_init = true;
    }

    dwconv_fused<<<dim3(7, 12, BB), 256, dw_smem>>>(x, dwk);
    wfold_kernel<<<dim3(CC, 3), CC>>>(bn2g, bn2b, pww, pwb);
    gemm_mma_kernel<<<7056, 256, gemm_smem>>>();
    kv_kernel<<<BB*HEADS, 256>>>();
    att_kernel<<<dim3(BB, LL/32), 384, att_smem>>>(x, addw);
    bn1_final_kernel<<<1, CC>>>();
    bn1_apply_kernel<<<2048, 256>>>(bn1g, bn1b, out);
}